// round 3
// baseline (speedup 1.0000x reference)
#include <cuda_runtime.h>
#include <cstddef>

// ============================================================================
// MotionGenerator: fused masked-conv1d(stride2,reflect pad7,K15) + pool + leakyrelu
//
// Structure (hardcoded from the reference's constant EDGES/mask/pool_w):
//   21 joints, 64 in-ch/joint, 128 out-ch/joint, 12 pool groups x 128 ch.
//   85 nonzero (group, joint) blocks out of 12*21.
//
// Pass 1 (prep): fold mask + pooling into compact weights
//   Wc[slot][k][ci][oc]  (slot = (group, jj) pair, 85 slots)
// Pass 2 (main): block-sparse implicit GEMM, tile = 128 oc x 128 t per block.
//   x window per joint cached in smem, split by parity so each tap k is a
//   unit-stride shifted window (stride-2 conv trick).
// ============================================================================

#define NG 12
#define NSLOT 85
#define XPITCH 136          // parity-array row pitch (floats)
#define SMEM_FLOATS (64*XPITCH*2 + 64*128)   // xe + xo + Ws = 25600 floats = 100 KB

__constant__ int   cOff[NG + 1] = {0, 8, 19, 26, 35, 39, 48, 52, 61, 65, 74, 78, 85};
__constant__ int   cE0[NG] = {0, 1, 3, 4, 6, 8, 10, 12, 14, 16, 18, 20};
__constant__ int   cE1[NG] = {-1, 2, -1, 5, 7, 9, 11, 13, 15, 17, 19, -1};

__constant__ int cSlotG[NSLOT] = {
    0,0,0,0,0,0,0,0,
    1,1,1,1,1,1,1,1,1,1,1,
    2,2,2,2,2,2,2,
    3,3,3,3,3,3,3,3,3,
    4,4,4,4,
    5,5,5,5,5,5,5,5,5,
    6,6,6,6,
    7,7,7,7,7,7,7,7,7,
    8,8,8,8,
    9,9,9,9,9,9,9,9,9,
    10,10,10,10,
    11,11,11,11,11,11,11
};

__constant__ int cJ[NSLOT] = {
    0,1,2,12,13,16,17,20,                    // g0  [e0]
    0,1,2,3,4,5,8,9,12,16,20,                // g1  [e1,e2]
    1,2,3,4,5,8,9,                           // g2  [e3]
    1,2,3,4,5,6,7,8,9,                       // g3  [e4,e5]
    4,5,6,7,                                 // g4  [e6,e7]
    1,2,3,4,5,8,9,10,11,                     // g5  [e8,e9]
    8,9,10,11,                               // g6  [e10,e11]
    0,1,12,13,14,15,16,17,20,                // g7  [e12,e13]
    12,13,14,15,                             // g8  [e14,e15]
    0,1,12,13,16,17,18,19,20,                // g9  [e16,e17]
    16,17,18,19,                             // g10 [e18,e19]
    0,1,2,12,13,16,17                        // g11 [global row 20]
};

__constant__ float cC0[NSLOT] = {
    1,1,1,1,1,1,1,1,
    0.5f,0.5f,0.5f,0.5f,0.5f,0.0f,0.5f,0.0f,0.5f,0.5f,0.5f,
    1,1,1,1,1,1,1,
    0.5f,0.5f,0.5f,0.5f,0.5f,0.5f,0.0f,0.5f,0.5f,
    0.5f,0.5f,0.5f,0.5f,
    0.5f,0.5f,0.5f,0.5f,0.5f,0.5f,0.5f,0.5f,0.0f,
    0.5f,0.5f,0.5f,0.5f,
    0.5f,0.5f,0.5f,0.5f,0.5f,0.0f,0.5f,0.5f,0.5f,
    0.5f,0.5f,0.5f,0.5f,
    0.5f,0.5f,0.5f,0.5f,0.5f,0.5f,0.5f,0.0f,0.5f,
    0.5f,0.5f,0.5f,0.5f,
    1,1,1,1,1,1,1
};

__constant__ float cC1[NSLOT] = {
    0,0,0,0,0,0,0,0,
    0.5f,0.5f,0.5f,0.5f,0.5f,0.5f,0.5f,0.5f,0.0f,0.0f,0.5f,
    0,0,0,0,0,0,0,
    0.0f,0.5f,0.5f,0.5f,0.5f,0.5f,0.5f,0.5f,0.0f,
    0.0f,0.5f,0.5f,0.5f,
    0.0f,0.5f,0.5f,0.5f,0.0f,0.5f,0.5f,0.5f,0.5f,
    0.0f,0.5f,0.5f,0.5f,
    0.5f,0.0f,0.5f,0.5f,0.5f,0.5f,0.5f,0.0f,0.5f,
    0.0f,0.5f,0.5f,0.5f,
    0.5f,0.0f,0.5f,0.0f,0.5f,0.5f,0.5f,0.5f,0.5f,   // g9: j=20 coef FIXED 0.0 -> 0.5
    0.0f,0.5f,0.5f,0.5f,
    0,0,0,0,0,0,0
};

// Compacted folded weights: [85 slots][15 taps][64 ci][128 oc] = 41.8 MB
__device__ __align__(16) float g_Wc[(size_t)NSLOT * 15 * 64 * 128];

// ----------------------------------------------------------------------------
// Prep: Wc[s][k][ci][oc] = c0*weight[e0*128+oc, j*64+ci, k] + c1*weight[e1...]
// weight layout: [2688][1344][15] row-major -> row stride 20160
// ----------------------------------------------------------------------------
__global__ void prep_wc(const float* __restrict__ weight) {
    const int s  = blockIdx.x;   // 0..84
    const int oc = blockIdx.y;   // 0..127
    const int g  = cSlotG[s];
    const int j  = cJ[s];
    const float c0 = cC0[s], c1 = cC1[s];
    const int e0 = cE0[g], e1 = cE1[g];

    const float* __restrict__ w0 = weight + (size_t)(e0 * 128 + oc) * 20160 + (size_t)j * 960;
    const float* __restrict__ w1 = (e1 >= 0)
        ? weight + (size_t)(e1 * 128 + oc) * 20160 + (size_t)j * 960 : nullptr;

    for (int q = threadIdx.x; q < 960; q += blockDim.x) {
        float v = c0 * w0[q];
        if (w1) v += c1 * w1[q];
        const int ci = q / 15;
        const int k  = q - ci * 15;
        g_Wc[(((size_t)s * 15 + k) * 64 + ci) * 128 + oc] = v;
    }
}

// ----------------------------------------------------------------------------
// Main: block = (group g, t-tile, batch). Tile 128 oc x 128 t, 256 threads,
// each thread 8 oc x 8 t (t strided by 16 -> conflict-free smem reads).
// ----------------------------------------------------------------------------
__global__ __launch_bounds__(256, 2)
void motion_main(const float* __restrict__ x,
                 const float* __restrict__ bias,
                 float* __restrict__ out) {
    extern __shared__ float sm[];
    float* xe = sm;                      // [64][XPITCH]  even positions
    float* xo = sm + 64 * XPITCH;        // [64][XPITCH]  odd positions
    float* Ws = sm + 2 * 64 * XPITCH;    // [64 ci][128 oc]

    const int g    = blockIdx.x;    // 0..11
    const int tile = blockIdx.y;    // 0..15
    const int b    = blockIdx.z;    // 0..7
    const int tid  = threadIdx.x;
    const int ty   = tid >> 4;      // 0..15 -> oc block
    const int tx   = tid & 15;      // 0..15 -> t lane
    const int warp = tid >> 5, lane = tid & 31;

    const int t0   = tile << 7;
    const int base = 2 * t0 - 7;    // leftmost (unreflected) x position of window

    float acc[8][8];
#pragma unroll
    for (int i = 0; i < 8; ++i)
#pragma unroll
        for (int u = 0; u < 8; ++u) acc[i][u] = 0.f;

    const int off0 = cOff[g];
    const int nj   = cOff[g + 1] - off0;

    for (int jj = 0; jj < nj; ++jj) {
        const int s = off0 + jj;
        const int j = cJ[s];

        __syncthreads();   // previous iteration's compute must be done (xe/xo/Ws reuse)

        // ---- load x window for joint j: 64 ch x 269 positions, parity split ----
        const float* __restrict__ xj = x + ((size_t)b * 1344 + (size_t)j * 64) * 4096;
        for (int ci = warp; ci < 64; ci += 8) {
            const float* __restrict__ src = xj + (size_t)ci * 4096;
            for (int r = lane; r < 269; r += 32) {
                int pos = base + r;
                pos = pos < 0 ? -pos : pos;
                pos = pos > 4095 ? 8190 - pos : pos;   // reflect
                const float v = src[pos];
                if (r & 1) xo[ci * XPITCH + (r >> 1)] = v;
                else       xe[ci * XPITCH + (r >> 1)] = v;
            }
        }

        const float4* __restrict__ wsrc_base =
            reinterpret_cast<const float4*>(g_Wc) + (size_t)s * 15 * 2048;

        for (int k = 0; k < 15; ++k) {
            __syncthreads();   // prior compute done before overwriting Ws
            // ---- stage Wc[s][k] chunk: 64 ci x 128 oc ----
            const float4* __restrict__ wsrc = wsrc_base + (size_t)k * 2048;
            float4* wdst = reinterpret_cast<float4*>(Ws);
#pragma unroll
            for (int i = 0; i < 8; ++i) wdst[tid + (i << 8)] = wsrc[tid + (i << 8)];
            __syncthreads();

            // tap k reads parity array (k odd -> xo, k even -> xe) at shift k>>1
            const float* __restrict__ xrow = ((k & 1) ? xo : xe) + tx + (k >> 1);
            const float* __restrict__ wrow = Ws + (ty << 3);

#pragma unroll 2
            for (int ci = 0; ci < 64; ++ci) {
                const float4 a0 = *reinterpret_cast<const float4*>(wrow + ci * 128);
                const float4 a1 = *reinterpret_cast<const float4*>(wrow + ci * 128 + 4);
                float xb[8];
#pragma unroll
                for (int u = 0; u < 8; ++u) xb[u] = xrow[ci * XPITCH + (u << 4)];
                const float a[8] = {a0.x, a0.y, a0.z, a0.w, a1.x, a1.y, a1.z, a1.w};
#pragma unroll
                for (int i = 0; i < 8; ++i)
#pragma unroll
                    for (int u = 0; u < 8; ++u)
                        acc[i][u] = fmaf(a[i], xb[u], acc[i][u]);
            }
        }
    }

    // ---- epilogue: pooled bias + leaky relu(0.2), write out[b][g*128+oc][t] ----
    const int e0 = cE0[g], e1 = cE1[g];
    const float sc = (e1 >= 0) ? 0.5f : 1.0f;
    float* __restrict__ orow =
        out + ((size_t)b * 1536 + (size_t)(g << 7) + (size_t)(ty << 3)) * 2048 + t0 + tx;
#pragma unroll
    for (int i = 0; i < 8; ++i) {
        const int oc = (ty << 3) + i;
        float bv = bias[e0 * 128 + oc];
        if (e1 >= 0) bv += bias[e1 * 128 + oc];
        bv *= sc;
#pragma unroll
        for (int u = 0; u < 8; ++u) {
            float v = acc[i][u] + bv;
            v = v > 0.f ? v : 0.2f * v;
            orow[(size_t)i * 2048 + (u << 4)] = v;
        }
    }
}

// ----------------------------------------------------------------------------
extern "C" void kernel_launch(void* const* d_in, const int* in_sizes, int n_in,
                              void* d_out, int out_size) {
    (void)in_sizes; (void)n_in; (void)out_size;
    const float* x      = (const float*)d_in[0];   // [8][1344][4096]
    const float* weight = (const float*)d_in[1];   // [2688][1344][15]
    const float* bias   = (const float*)d_in[2];   // [2688]
    float* out          = (float*)d_out;           // [8][1536][2048]

    cudaFuncSetAttribute(motion_main, cudaFuncAttributeMaxDynamicSharedMemorySize,
                         SMEM_FLOATS * (int)sizeof(float));

    dim3 gp(NSLOT, 128);
    prep_wc<<<gp, 256>>>(weight);

    dim3 gm(NG, 16, 8);
    motion_main<<<gm, 256, SMEM_FLOATS * sizeof(float)>>>(x, bias, out);
}

// round 5
// speedup vs baseline: 2.4275x; 2.4275x over previous
#include <cuda_runtime.h>
#include <cuda_bf16.h>
#include <cstdint>
#include <cstddef>

// ============================================================================
// MotionGenerator fused: masked-conv1d(stride2,reflect7,K15)+pool+leakyReLU
// via warp-level mma.sync.m16n8k16 bf16 (split hi/lo precision, fp32 accum).
// tcgen05 is NOT available (harness compiles compute_103, non-'a' target).
//
//   D[t=128][oc=128] per CTA = sum over (joint slot, tap k, ci=64) of
//       x[ci][2(t0+t)+k-7] * Wc[slot][k][oc][ci]
// ============================================================================

#define NG 12
#define NSLOT 85

__constant__ int   cOff[NG + 1] = {0, 8, 19, 26, 35, 39, 48, 52, 61, 65, 74, 78, 85};
__constant__ int   cE0[NG] = {0, 1, 3, 4, 6, 8, 10, 12, 14, 16, 18, 20};
__constant__ int   cE1[NG] = {-1, 2, -1, 5, 7, 9, 11, 13, 15, 17, 19, -1};

__constant__ int cSlotG[NSLOT] = {
    0,0,0,0,0,0,0,0,
    1,1,1,1,1,1,1,1,1,1,1,
    2,2,2,2,2,2,2,
    3,3,3,3,3,3,3,3,3,
    4,4,4,4,
    5,5,5,5,5,5,5,5,5,
    6,6,6,6,
    7,7,7,7,7,7,7,7,7,
    8,8,8,8,
    9,9,9,9,9,9,9,9,9,
    10,10,10,10,
    11,11,11,11,11,11,11
};

__constant__ int cJ[NSLOT] = {
    0,1,2,12,13,16,17,20,
    0,1,2,3,4,5,8,9,12,16,20,
    1,2,3,4,5,8,9,
    1,2,3,4,5,6,7,8,9,
    4,5,6,7,
    1,2,3,4,5,8,9,10,11,
    8,9,10,11,
    0,1,12,13,14,15,16,17,20,
    12,13,14,15,
    0,1,12,13,16,17,18,19,20,
    16,17,18,19,
    0,1,2,12,13,16,17
};

__constant__ float cC0[NSLOT] = {
    1,1,1,1,1,1,1,1,
    0.5f,0.5f,0.5f,0.5f,0.5f,0.0f,0.5f,0.0f,0.5f,0.5f,0.5f,
    1,1,1,1,1,1,1,
    0.5f,0.5f,0.5f,0.5f,0.5f,0.5f,0.0f,0.5f,0.5f,
    0.5f,0.5f,0.5f,0.5f,
    0.5f,0.5f,0.5f,0.5f,0.5f,0.5f,0.5f,0.5f,0.0f,
    0.5f,0.5f,0.5f,0.5f,
    0.5f,0.5f,0.5f,0.5f,0.5f,0.0f,0.5f,0.5f,0.5f,
    0.5f,0.5f,0.5f,0.5f,
    0.5f,0.5f,0.5f,0.5f,0.5f,0.5f,0.5f,0.0f,0.5f,
    0.5f,0.5f,0.5f,0.5f,
    1,1,1,1,1,1,1
};

__constant__ float cC1[NSLOT] = {
    0,0,0,0,0,0,0,0,
    0.5f,0.5f,0.5f,0.5f,0.5f,0.5f,0.5f,0.5f,0.0f,0.0f,0.5f,
    0,0,0,0,0,0,0,
    0.0f,0.5f,0.5f,0.5f,0.5f,0.5f,0.5f,0.5f,0.0f,
    0.0f,0.5f,0.5f,0.5f,
    0.0f,0.5f,0.5f,0.5f,0.0f,0.5f,0.5f,0.5f,0.5f,
    0.0f,0.5f,0.5f,0.5f,
    0.5f,0.0f,0.5f,0.5f,0.5f,0.5f,0.5f,0.0f,0.5f,
    0.0f,0.5f,0.5f,0.5f,
    0.5f,0.0f,0.5f,0.0f,0.5f,0.5f,0.5f,0.5f,0.5f,
    0.0f,0.5f,0.5f,0.5f,
    0,0,0,0,0,0,0
};

// Folded weights, bf16 hi/lo, dense [s][k][oc=128][ci=64]  (16KB per (s,k,prec))
__device__ __align__(16) __nv_bfloat16 g_Wh[(size_t)NSLOT * 15 * 8192];
__device__ __align__(16) __nv_bfloat16 g_Wl[(size_t)NSLOT * 15 * 8192];

// ---------------------------------------------------------------------------
// smem layout (bytes):
//   [0, 512)            pooled bias (128 f32)
//   [512, 512+78336)    A: [prec(2)][parity(2)][q=136 rows][72 bf16] pitch 144B
//   [79?  ...]          B: 2 buffers x (hi 18432B + lo 18432B)
// Epilogue reuses the A region as D-transpose staging [oc=128][132 f32].
// ---------------------------------------------------------------------------
#define AP   72                      // A/B row pitch in bf16 elems (144 B)
#define ASZ  (136 * AP)              // 9792 elems = 19584 B per (prec,parity)
#define BSZ  (128 * AP)              // 9216 elems = 18432 B per prec
#define A_OFF 512
#define B_OFF (A_OFF + 4 * ASZ * 2)  // 512 + 78336 = 78848
#define SMEM_BYTES (B_OFF + 2 * 2 * BSZ * 2)   // + 73728 = 152576

__device__ __forceinline__ uint32_t smem_u32(const void* p) {
    uint32_t a;
    asm("{ .reg .u64 t; cvta.to.shared.u64 t, %1; cvt.u32.u64 %0, t; }" : "=r"(a) : "l"(p));
    return a;
}

__device__ __forceinline__ void mma16816(float* d, uint32_t a0, uint32_t a1,
                                         uint32_t a2, uint32_t a3,
                                         uint32_t b0, uint32_t b1) {
    asm volatile(
        "mma.sync.aligned.m16n8k16.row.col.f32.bf16.bf16.f32 "
        "{%0,%1,%2,%3}, {%4,%5,%6,%7}, {%8,%9}, {%0,%1,%2,%3};"
        : "+f"(d[0]), "+f"(d[1]), "+f"(d[2]), "+f"(d[3])
        : "r"(a0), "r"(a1), "r"(a2), "r"(a3), "r"(b0), "r"(b1));
}

// ---------------------------------------------------------------------------
// Prep: fold mask+pool, split fp32 -> bf16 hi + bf16 lo, dense tiles.
// weight layout [2688][1344][15], row stride 20160.
// ---------------------------------------------------------------------------
__global__ void prep_wc(const float* __restrict__ weight) {
    const int s  = blockIdx.x;   // 0..84
    const int oc = blockIdx.y;   // 0..127
    const int g  = cSlotG[s];
    const int j  = cJ[s];
    const float c0 = cC0[s], c1 = cC1[s];
    const int e0 = cE0[g], e1 = cE1[g];

    const float* __restrict__ w0 = weight + (size_t)(e0 * 128 + oc) * 20160 + (size_t)j * 960;
    const float* __restrict__ w1 = (e1 >= 0)
        ? weight + (size_t)(e1 * 128 + oc) * 20160 + (size_t)j * 960 : nullptr;

    for (int q = threadIdx.x; q < 960; q += blockDim.x) {
        float v = c0 * w0[q];
        if (w1) v += c1 * w1[q];
        const int ci = q / 15;
        const int k  = q - ci * 15;
        __nv_bfloat16 h = __float2bfloat16(v);
        __nv_bfloat16 l = __float2bfloat16(v - __bfloat162float(h));
        const size_t idx = ((size_t)(s * 15 + k) * 128 + oc) * 64 + ci;
        g_Wh[idx] = h;
        g_Wl[idx] = l;
    }
}

// ---------------------------------------------------------------------------
// Main: 256 threads, 8 warps (4 in t x 2 in oc), tile 128t x 128oc.
// ---------------------------------------------------------------------------
__global__ __launch_bounds__(256, 1)
void motion_hmma(const float* __restrict__ x,
                 const float* __restrict__ bias,
                 float* __restrict__ out) {
    extern __shared__ __align__(16) char smem[];
    float* sbias = reinterpret_cast<float*>(smem);
    __nv_bfloat16* Aarr = reinterpret_cast<__nv_bfloat16*>(smem + A_OFF);
    char* Bbase = smem + B_OFF;
    const uint32_t Bsm = smem_u32(Bbase);

    const int tid  = threadIdx.x;
    const int w    = tid >> 5;
    const int lane = tid & 31;

    const int tile = blockIdx.x;   // 0..15
    const int b    = blockIdx.y;   // 0..7
    const int g    = blockIdx.z;   // 0..11
    const int t0   = tile << 7;
    const int base = 2 * t0 - 7;

    const int warp_tm = (w & 3) * 32;   // t offset of this warp
    const int warp_on = (w >> 2) * 64;  // oc offset

    // pooled bias
    if (tid < 128) {
        const int e0 = cE0[g], e1 = cE1[g];
        float bv = bias[e0 * 128 + tid];
        if (e1 >= 0) bv = 0.5f * (bv + bias[e1 * 128 + tid]);
        sbias[tid] = bv;
    }

    float acc[2][8][4];
#pragma unroll
    for (int mi = 0; mi < 2; ++mi)
#pragma unroll
        for (int ni = 0; ni < 8; ++ni)
#pragma unroll
            for (int q = 0; q < 4; ++q) acc[mi][ni][q] = 0.f;

    const int off0 = cOff[g];
    const int nj   = cOff[g + 1] - off0;
    const int nt   = nj * 15;

    // ---- cp.async issue of tap n's B tile (hi+lo, 32KB) into buf n&1 ----
    auto issue = [&](int n) {
        const int s = off0 + n / 15;
        const int k = n - (n / 15) * 15;
        const int buf = n & 1;
        const size_t tbase = (size_t)(s * 15 + k) * 8192;
#pragma unroll
        for (int i = 0; i < 8; ++i) {
            const int c = tid + (i << 8);         // 0..2047
            const int prec = c >> 10;             // 0 hi, 1 lo
            const int row  = (c >> 3) & 127;      // oc
            const int col  = c & 7;               // 16B chunk in 128B row
            const __nv_bfloat16* src =
                (prec ? g_Wl : g_Wh) + tbase + (size_t)row * 64 + col * 8;
            const uint32_t dst = Bsm + buf * (2 * BSZ * 2) + prec * (BSZ * 2)
                               + row * 144 + col * 16;
            asm volatile("cp.async.cg.shared.global [%0], [%1], 16;"
                         :: "r"(dst), "l"(src) : "memory");
        }
        asm volatile("cp.async.commit_group;" ::: "memory");
    };

    issue(0);

    const int colb = (lane & 3) * 2;
    const int grow = lane >> 2;

    for (int jj = 0; jj < nj; ++jj) {
        const int j = cJ[off0 + jj];

        // ---- window load: x[ci][pos] -> A[prec][parity][q][ci], bf16 split ----
        // (previous tap's compute finished at its trailing __syncthreads)
        {
            const float* __restrict__ xj = x + ((size_t)b * 1344 + (size_t)j * 64) * 4096;
            for (int ci = w; ci < 64; ci += 8) {
                const float* __restrict__ src = xj + (size_t)ci * 4096;
                for (int r = lane; r < 269; r += 32) {
                    int pos = base + r;
                    pos = pos < 0 ? -pos : pos;
                    pos = pos > 4095 ? 8190 - pos : pos;
                    const float v = src[pos];
                    const __nv_bfloat16 h = __float2bfloat16(v);
                    const __nv_bfloat16 l = __float2bfloat16(v - __bfloat162float(h));
                    const int par = r & 1, q = r >> 1;
                    Aarr[(size_t)par * ASZ + q * AP + ci] = h;          // prec 0
                    Aarr[(size_t)(2 + par) * ASZ + q * AP + ci] = l;    // prec 1
                }
            }
        }

        for (int k = 0; k < 15; ++k) {
            const int n = jj * 15 + k;
            if (n + 1 < nt) {
                issue(n + 1);
                asm volatile("cp.async.wait_group 1;" ::: "memory");
            } else {
                asm volatile("cp.async.wait_group 0;" ::: "memory");
            }
            __syncthreads();   // B tile ready + window/A writes visible

            const __nv_bfloat16* Ah_p = Aarr + (size_t)(k & 1) * ASZ;
            const __nv_bfloat16* Al_p = Aarr + (size_t)(2 + (k & 1)) * ASZ;
            const __nv_bfloat16* Bh =
                reinterpret_cast<const __nv_bfloat16*>(Bbase + (n & 1) * (2 * BSZ * 2));
            const __nv_bfloat16* Bl = Bh + BSZ;

            const int ra = warp_tm + (k >> 1) + grow;   // A row (q) for mi=0

#pragma unroll
            for (int cc = 0; cc < 4; ++cc) {
                const int col = cc * 16 + colb;
                uint32_t ah[2][4], al[2][4];
#pragma unroll
                for (int mi = 0; mi < 2; ++mi) {
                    const int r0 = ra + mi * 16;
                    ah[mi][0] = *reinterpret_cast<const uint32_t*>(Ah_p + r0 * AP + col);
                    ah[mi][1] = *reinterpret_cast<const uint32_t*>(Ah_p + (r0 + 8) * AP + col);
                    ah[mi][2] = *reinterpret_cast<const uint32_t*>(Ah_p + r0 * AP + col + 8);
                    ah[mi][3] = *reinterpret_cast<const uint32_t*>(Ah_p + (r0 + 8) * AP + col + 8);
                    al[mi][0] = *reinterpret_cast<const uint32_t*>(Al_p + r0 * AP + col);
                    al[mi][1] = *reinterpret_cast<const uint32_t*>(Al_p + (r0 + 8) * AP + col);
                    al[mi][2] = *reinterpret_cast<const uint32_t*>(Al_p + r0 * AP + col + 8);
                    al[mi][3] = *reinterpret_cast<const uint32_t*>(Al_p + (r0 + 8) * AP + col + 8);
                }
#pragma unroll
                for (int ni = 0; ni < 8; ++ni) {
                    const int rb = warp_on + ni * 8 + grow;
                    const uint32_t bh0 = *reinterpret_cast<const uint32_t*>(Bh + rb * AP + col);
                    const uint32_t bh1 = *reinterpret_cast<const uint32_t*>(Bh + rb * AP + col + 8);
                    const uint32_t bl0 = *reinterpret_cast<const uint32_t*>(Bl + rb * AP + col);
                    const uint32_t bl1 = *reinterpret_cast<const uint32_t*>(Bl + rb * AP + col + 8);
#pragma unroll
                    for (int mi = 0; mi < 2; ++mi) {
                        mma16816(acc[mi][ni], ah[mi][0], ah[mi][1], ah[mi][2], ah[mi][3], bh0, bh1);
                        mma16816(acc[mi][ni], ah[mi][0], ah[mi][1], ah[mi][2], ah[mi][3], bl0, bl1);
                        mma16816(acc[mi][ni], al[mi][0], al[mi][1], al[mi][2], al[mi][3], bh0, bh1);
                    }
                }
            }
            __syncthreads();   // compute done before buf/A overwrite
        }
    }

    // ---- epilogue: transpose D through smem (A region), bias+leakyrelu ----
    float* Ds = reinterpret_cast<float*>(smem + A_OFF);   // [oc=128][pitch 132]
#pragma unroll
    for (int mi = 0; mi < 2; ++mi) {
        const int row = warp_tm + mi * 16 + grow;
#pragma unroll
        for (int ni = 0; ni < 8; ++ni) {
            const int col = warp_on + ni * 8 + colb;
            Ds[(col    ) * 132 + row    ] = acc[mi][ni][0];
            Ds[(col + 1) * 132 + row    ] = acc[mi][ni][1];
            Ds[(col    ) * 132 + row + 8] = acc[mi][ni][2];
            Ds[(col + 1) * 132 + row + 8] = acc[mi][ni][3];
        }
    }
    __syncthreads();

    {
        const int oc = tid >> 1, half = tid & 1;
        const float bv = sbias[oc];
        const float4* __restrict__ sp =
            reinterpret_cast<const float4*>(Ds + oc * 132 + half * 64);
        float4* __restrict__ op = reinterpret_cast<float4*>(
            out + ((size_t)b * 1536 + (size_t)g * 128 + oc) * 2048 + t0 + half * 64);
#pragma unroll
        for (int i = 0; i < 16; ++i) {
            float4 v = sp[i];
            v.x += bv; v.y += bv; v.z += bv; v.w += bv;
            v.x = v.x > 0.f ? v.x : 0.2f * v.x;
            v.y = v.y > 0.f ? v.y : 0.2f * v.y;
            v.z = v.z > 0.f ? v.z : 0.2f * v.z;
            v.w = v.w > 0.f ? v.w : 0.2f * v.w;
            op[i] = v;
        }
    }
}

// ---------------------------------------------------------------------------
extern "C" void kernel_launch(void* const* d_in, const int* in_sizes, int n_in,
                              void* d_out, int out_size) {
    (void)in_sizes; (void)n_in; (void)out_size;
    const float* x      = (const float*)d_in[0];   // [8][1344][4096]
    const float* weight = (const float*)d_in[1];   // [2688][1344][15]
    const float* bias   = (const float*)d_in[2];   // [2688]
    float* out          = (float*)d_out;           // [8][1536][2048]

    cudaFuncSetAttribute(motion_hmma, cudaFuncAttributeMaxDynamicSharedMemorySize,
                         SMEM_BYTES);

    dim3 gp(NSLOT, 128);
    prep_wc<<<gp, 256>>>(weight);

    // z = g slow-varying: concurrent CTAs share the per-tap 32KB weight tile in L2
    dim3 gm(16, 8, NG);
    motion_hmma<<<gm, 256, SMEM_BYTES>>>(x, bias, out);
}

// round 6
// speedup vs baseline: 4.2990x; 1.7709x over previous
#include <cuda_runtime.h>
#include <cuda_fp16.h>
#include <cstdint>
#include <cstddef>

// ============================================================================
// MotionGenerator fused: masked-conv1d(stride2,reflect7,K15)+pool+leakyReLU
// via warp-level mma.sync.m16n8k16 fp16 (A split hi+lo, B hi; fp32 accum).
//   D = (Ah + Al) * Bh  -> A exact to ~2^-22, residual = B rounding ~2^-11.
// 2 CTAs/SM target: smem 115136 B, __launch_bounds__(256,2).
// ============================================================================

#define NG 12
#define NSLOT 85

__constant__ int   cOff[NG + 1] = {0, 8, 19, 26, 35, 39, 48, 52, 61, 65, 74, 78, 85};
__constant__ int   cE0[NG] = {0, 1, 3, 4, 6, 8, 10, 12, 14, 16, 18, 20};
__constant__ int   cE1[NG] = {-1, 2, -1, 5, 7, 9, 11, 13, 15, 17, 19, -1};

__constant__ int cSlotG[NSLOT] = {
    0,0,0,0,0,0,0,0,
    1,1,1,1,1,1,1,1,1,1,1,
    2,2,2,2,2,2,2,
    3,3,3,3,3,3,3,3,3,
    4,4,4,4,
    5,5,5,5,5,5,5,5,5,
    6,6,6,6,
    7,7,7,7,7,7,7,7,7,
    8,8,8,8,
    9,9,9,9,9,9,9,9,9,
    10,10,10,10,
    11,11,11,11,11,11,11
};

__constant__ int cJ[NSLOT] = {
    0,1,2,12,13,16,17,20,
    0,1,2,3,4,5,8,9,12,16,20,
    1,2,3,4,5,8,9,
    1,2,3,4,5,6,7,8,9,
    4,5,6,7,
    1,2,3,4,5,8,9,10,11,
    8,9,10,11,
    0,1,12,13,14,15,16,17,20,
    12,13,14,15,
    0,1,12,13,16,17,18,19,20,
    16,17,18,19,
    0,1,2,12,13,16,17
};

__constant__ float cC0[NSLOT] = {
    1,1,1,1,1,1,1,1,
    0.5f,0.5f,0.5f,0.5f,0.5f,0.0f,0.5f,0.0f,0.5f,0.5f,0.5f,
    1,1,1,1,1,1,1,
    0.5f,0.5f,0.5f,0.5f,0.5f,0.5f,0.0f,0.5f,0.5f,
    0.5f,0.5f,0.5f,0.5f,
    0.5f,0.5f,0.5f,0.5f,0.5f,0.5f,0.5f,0.5f,0.0f,
    0.5f,0.5f,0.5f,0.5f,
    0.5f,0.5f,0.5f,0.5f,0.5f,0.0f,0.5f,0.5f,0.5f,
    0.5f,0.5f,0.5f,0.5f,
    0.5f,0.5f,0.5f,0.5f,0.5f,0.5f,0.5f,0.0f,0.5f,
    0.5f,0.5f,0.5f,0.5f,
    1,1,1,1,1,1,1
};

__constant__ float cC1[NSLOT] = {
    0,0,0,0,0,0,0,0,
    0.5f,0.5f,0.5f,0.5f,0.5f,0.5f,0.5f,0.5f,0.0f,0.0f,0.5f,
    0,0,0,0,0,0,0,
    0.0f,0.5f,0.5f,0.5f,0.5f,0.5f,0.5f,0.5f,0.0f,
    0.0f,0.5f,0.5f,0.5f,
    0.0f,0.5f,0.5f,0.5f,0.0f,0.5f,0.5f,0.5f,0.5f,
    0.0f,0.5f,0.5f,0.5f,
    0.5f,0.0f,0.5f,0.5f,0.5f,0.5f,0.5f,0.0f,0.5f,
    0.0f,0.5f,0.5f,0.5f,
    0.5f,0.0f,0.5f,0.0f,0.5f,0.5f,0.5f,0.5f,0.5f,
    0.0f,0.5f,0.5f,0.5f,
    0,0,0,0,0,0,0
};

// Folded weights, fp16 hi only, dense [s][k][oc=128][ci=64]
__device__ __align__(16) __half g_Wh[(size_t)NSLOT * 15 * 8192];

// ---------------------------------------------------------------------------
// smem layout (bytes):
//   [0, 512)     pooled bias (128 f32)
//   [512, +77760)  A: [prec(2)][parity(2)][q=135 rows][72 halves], pitch 144B
//   [78272, +36864) B: 2 buffers x 18432B ([oc=128][72 halves])
// Epilogue reuses A region as D staging [oc=128][pitch 132 f32] (67584B).
// ---------------------------------------------------------------------------
#define AP    72
#define AROWS 135
#define ASZ   (AROWS * AP)            // 9720 halves per (prec,parity)
#define A_OFF 512
#define BSZB  18432                   // 128 * 144 bytes per buffer
#define B_OFF (A_OFF + 4 * ASZ * 2)   // 78272
#define SMEM_BYTES (B_OFF + 2 * BSZB) // 115136

__device__ __forceinline__ uint32_t smem_u32(const void* p) {
    uint32_t a;
    asm("{ .reg .u64 t; cvta.to.shared.u64 t, %1; cvt.u32.u64 %0, t; }" : "=r"(a) : "l"(p));
    return a;
}

__device__ __forceinline__ void mma16816(float* d, uint32_t a0, uint32_t a1,
                                         uint32_t a2, uint32_t a3,
                                         uint32_t b0, uint32_t b1) {
    asm volatile(
        "mma.sync.aligned.m16n8k16.row.col.f32.f16.f16.f32 "
        "{%0,%1,%2,%3}, {%4,%5,%6,%7}, {%8,%9}, {%0,%1,%2,%3};"
        : "+f"(d[0]), "+f"(d[1]), "+f"(d[2]), "+f"(d[3])
        : "r"(a0), "r"(a1), "r"(a2), "r"(a3), "r"(b0), "r"(b1));
}

// ---------------------------------------------------------------------------
// Prep: fold mask+pool -> fp16 hi, dense [s][k][oc][ci].
// weight layout [2688][1344][15], row stride 20160.
// ---------------------------------------------------------------------------
__global__ void prep_wc(const float* __restrict__ weight) {
    const int s  = blockIdx.x;
    const int oc = blockIdx.y;
    const int g  = cSlotG[s];
    const int j  = cJ[s];
    const float c0 = cC0[s], c1 = cC1[s];
    const int e0 = cE0[g], e1 = cE1[g];

    const float* __restrict__ w0 = weight + (size_t)(e0 * 128 + oc) * 20160 + (size_t)j * 960;
    const float* __restrict__ w1 = (e1 >= 0)
        ? weight + (size_t)(e1 * 128 + oc) * 20160 + (size_t)j * 960 : nullptr;

    for (int q = threadIdx.x; q < 960; q += blockDim.x) {
        float v = c0 * w0[q];
        if (w1) v += c1 * w1[q];
        const int ci = q / 15;
        const int k  = q - ci * 15;
        g_Wh[((size_t)(s * 15 + k) * 128 + oc) * 64 + ci] = __float2half_rn(v);
    }
}

// ---------------------------------------------------------------------------
// Main: 256 threads, 8 warps (4 in t x 2 in oc), tile 128t x 128oc.
// ---------------------------------------------------------------------------
__global__ __launch_bounds__(256, 2)
void motion_hmma(const float* __restrict__ x,
                 const float* __restrict__ bias,
                 float* __restrict__ out) {
    extern __shared__ __align__(16) char smem[];
    float* sbias = reinterpret_cast<float*>(smem);
    __half* Aarr = reinterpret_cast<__half*>(smem + A_OFF);
    char* Bbase  = smem + B_OFF;
    const uint32_t Bsm = smem_u32(Bbase);

    const int tid  = threadIdx.x;
    const int w    = tid >> 5;
    const int lane = tid & 31;

    const int tile = blockIdx.x;   // 0..15
    const int b    = blockIdx.y;   // 0..7
    const int g    = blockIdx.z;   // 0..11
    const int t0   = tile << 7;
    const int base = 2 * t0 - 7;

    const int warp_tm = (w & 3) * 32;
    const int warp_on = (w >> 2) * 64;

    if (tid < 128) {
        const int e0 = cE0[g], e1 = cE1[g];
        float bv = bias[e0 * 128 + tid];
        if (e1 >= 0) bv = 0.5f * (bv + bias[e1 * 128 + tid]);
        sbias[tid] = bv;
    }

    float acc[2][8][4];
#pragma unroll
    for (int mi = 0; mi < 2; ++mi)
#pragma unroll
        for (int ni = 0; ni < 8; ++ni)
#pragma unroll
            for (int q = 0; q < 4; ++q) acc[mi][ni][q] = 0.f;

    const int off0 = cOff[g];
    const int nj   = cOff[g + 1] - off0;
    const int nt   = nj * 15;

    // cp.async of tap n's Bh tile (18KB) into buf n&1: 1024 x 16B, 4 per thread
    auto issue = [&](int n) {
        const int s = off0 + n / 15;
        const int k = n - (n / 15) * 15;
        const size_t tbase = (size_t)(s * 15 + k) * 8192;
        const uint32_t dbase = Bsm + (uint32_t)(n & 1) * BSZB;
#pragma unroll
        for (int i = 0; i < 4; ++i) {
            const int c   = tid + (i << 8);       // 0..1023
            const int row = c >> 3;               // oc
            const int col = c & 7;                // 16B chunk
            const __half* src = g_Wh + tbase + (size_t)row * 64 + col * 8;
            const uint32_t dst = dbase + row * 144 + col * 16;
            asm volatile("cp.async.cg.shared.global [%0], [%1], 16;"
                         :: "r"(dst), "l"(src) : "memory");
        }
        asm volatile("cp.async.commit_group;" ::: "memory");
    };

    issue(0);

    const int colb = (lane & 3) * 2;
    const int grow = lane >> 2;

    for (int jj = 0; jj < nj; ++jj) {
        const int j = cJ[off0 + jj];

        // ---- window load: x -> Ah/Al per parity (prev tap ended with sync) ----
        {
            const float* __restrict__ xj = x + ((size_t)b * 1344 + (size_t)j * 64) * 4096;
            for (int ci = w; ci < 64; ci += 8) {
                const float* __restrict__ src = xj + (size_t)ci * 4096;
                for (int r = lane; r < 269; r += 32) {
                    int pos = base + r;
                    pos = pos < 0 ? -pos : pos;
                    pos = pos > 4095 ? 8190 - pos : pos;
                    const float v = src[pos];
                    const __half h = __float2half_rn(v);
                    const __half l = __float2half_rn(v - __half2float(h));
                    const int par = r & 1, q = r >> 1;
                    Aarr[(size_t)par * ASZ + q * AP + ci] = h;          // prec 0
                    Aarr[(size_t)(2 + par) * ASZ + q * AP + ci] = l;    // prec 1
                }
            }
        }

        for (int k = 0; k < 15; ++k) {
            const int n = jj * 15 + k;
            if (n + 1 < nt) {
                issue(n + 1);
                asm volatile("cp.async.wait_group 1;" ::: "memory");
            } else {
                asm volatile("cp.async.wait_group 0;" ::: "memory");
            }
            __syncthreads();   // B ready + A window visible

            const __half* Ah_p = Aarr + (size_t)(k & 1) * ASZ;
            const __half* Al_p = Aarr + (size_t)(2 + (k & 1)) * ASZ;
            const __half* Bh =
                reinterpret_cast<const __half*>(Bbase + (n & 1) * BSZB);

            const int ra = warp_tm + (k >> 1) + grow;

#pragma unroll
            for (int cc = 0; cc < 4; ++cc) {
                const int col = cc * 16 + colb;
                uint32_t ah[2][4], al[2][4];
#pragma unroll
                for (int mi = 0; mi < 2; ++mi) {
                    const int r0 = ra + mi * 16;
                    ah[mi][0] = *reinterpret_cast<const uint32_t*>(Ah_p + r0 * AP + col);
                    ah[mi][1] = *reinterpret_cast<const uint32_t*>(Ah_p + (r0 + 8) * AP + col);
                    ah[mi][2] = *reinterpret_cast<const uint32_t*>(Ah_p + r0 * AP + col + 8);
                    ah[mi][3] = *reinterpret_cast<const uint32_t*>(Ah_p + (r0 + 8) * AP + col + 8);
                    al[mi][0] = *reinterpret_cast<const uint32_t*>(Al_p + r0 * AP + col);
                    al[mi][1] = *reinterpret_cast<const uint32_t*>(Al_p + (r0 + 8) * AP + col);
                    al[mi][2] = *reinterpret_cast<const uint32_t*>(Al_p + r0 * AP + col + 8);
                    al[mi][3] = *reinterpret_cast<const uint32_t*>(Al_p + (r0 + 8) * AP + col + 8);
                }
#pragma unroll
                for (int ni = 0; ni < 8; ++ni) {
                    const int rb = warp_on + ni * 8 + grow;
                    const uint32_t b0 = *reinterpret_cast<const uint32_t*>(Bh + rb * AP + col);
                    const uint32_t b1 = *reinterpret_cast<const uint32_t*>(Bh + rb * AP + col + 8);
#pragma unroll
                    for (int mi = 0; mi < 2; ++mi) {
                        mma16816(acc[mi][ni], ah[mi][0], ah[mi][1], ah[mi][2], ah[mi][3], b0, b1);
                        mma16816(acc[mi][ni], al[mi][0], al[mi][1], al[mi][2], al[mi][3], b0, b1);
                    }
                }
            }
            __syncthreads();   // compute done before buf/A overwrite
        }
    }

    // ---- epilogue: transpose D via smem (A region), bias + leaky relu ----
    float* Ds = reinterpret_cast<float*>(smem + A_OFF);   // [128][132]
#pragma unroll
    for (int mi = 0; mi < 2; ++mi) {
        const int row = warp_tm + mi * 16 + grow;
#pragma unroll
        for (int ni = 0; ni < 8; ++ni) {
            const int col = warp_on + ni * 8 + colb;
            Ds[(col    ) * 132 + row    ] = acc[mi][ni][0];
            Ds[(col + 1) * 132 + row    ] = acc[mi][ni][1];
            Ds[(col    ) * 132 + row + 8] = acc[mi][ni][2];
            Ds[(col + 1) * 132 + row + 8] = acc[mi][ni][3];
        }
    }
    __syncthreads();

    {
        const int oc = tid >> 1, half = tid & 1;
        const float bv = sbias[oc];
        const float4* __restrict__ sp =
            reinterpret_cast<const float4*>(Ds + oc * 132 + half * 64);
        float4* __restrict__ op = reinterpret_cast<float4*>(
            out + ((size_t)b * 1536 + (size_t)g * 128 + oc) * 2048 + t0 + half * 64);
#pragma unroll
        for (int i = 0; i < 16; ++i) {
            float4 v = sp[i];
            v.x += bv; v.y += bv; v.z += bv; v.w += bv;
            v.x = v.x > 0.f ? v.x : 0.2f * v.x;
            v.y = v.y > 0.f ? v.y : 0.2f * v.y;
            v.z = v.z > 0.f ? v.z : 0.2f * v.z;
            v.w = v.w > 0.f ? v.w : 0.2f * v.w;
            op[i] = v;
        }
    }
}

// ---------------------------------------------------------------------------
extern "C" void kernel_launch(void* const* d_in, const int* in_sizes, int n_in,
                              void* d_out, int out_size) {
    (void)in_sizes; (void)n_in; (void)out_size;
    const float* x      = (const float*)d_in[0];   // [8][1344][4096]
    const float* weight = (const float*)d_in[1];   // [2688][1344][15]
    const float* bias   = (const float*)d_in[2];   // [2688]
    float* out          = (float*)d_out;           // [8][1536][2048]

    cudaFuncSetAttribute(motion_hmma, cudaFuncAttributeMaxDynamicSharedMemorySize,
                         SMEM_BYTES);

    dim3 gp(NSLOT, 128);
    prep_wc<<<gp, 256>>>(weight);

    dim3 gm(16, 8, NG);
    motion_hmma<<<gm, 256, SMEM_BYTES>>>(x, bias, out);
}

// round 7
// speedup vs baseline: 7.2871x; 1.6951x over previous
#include <cuda_runtime.h>
#include <cuda_fp16.h>
#include <cstdint>
#include <cstddef>

// ============================================================================
// MotionGenerator fused: masked-conv1d(stride2,reflect7,K15)+pool+leakyReLU
// via mma.sync.m16n8k16 fp16, single-term (Ah*Bh), fp32 accum.
// ldmatrix fragment loads, 4-deep cp.async B pipeline, 1 sync/tap.
// ============================================================================

#define NG 12
#define NSLOT 85

__constant__ int   cOff[NG + 1] = {0, 8, 19, 26, 35, 39, 48, 52, 61, 65, 74, 78, 85};
__constant__ int   cE0[NG] = {0, 1, 3, 4, 6, 8, 10, 12, 14, 16, 18, 20};
__constant__ int   cE1[NG] = {-1, 2, -1, 5, 7, 9, 11, 13, 15, 17, 19, -1};

__constant__ int cSlotG[NSLOT] = {
    0,0,0,0,0,0,0,0,
    1,1,1,1,1,1,1,1,1,1,1,
    2,2,2,2,2,2,2,
    3,3,3,3,3,3,3,3,3,
    4,4,4,4,
    5,5,5,5,5,5,5,5,5,
    6,6,6,6,
    7,7,7,7,7,7,7,7,7,
    8,8,8,8,
    9,9,9,9,9,9,9,9,9,
    10,10,10,10,
    11,11,11,11,11,11,11
};

__constant__ int cJ[NSLOT] = {
    0,1,2,12,13,16,17,20,
    0,1,2,3,4,5,8,9,12,16,20,
    1,2,3,4,5,8,9,
    1,2,3,4,5,6,7,8,9,
    4,5,6,7,
    1,2,3,4,5,8,9,10,11,
    8,9,10,11,
    0,1,12,13,14,15,16,17,20,
    12,13,14,15,
    0,1,12,13,16,17,18,19,20,
    16,17,18,19,
    0,1,2,12,13,16,17
};

__constant__ float cC0[NSLOT] = {
    1,1,1,1,1,1,1,1,
    0.5f,0.5f,0.5f,0.5f,0.5f,0.0f,0.5f,0.0f,0.5f,0.5f,0.5f,
    1,1,1,1,1,1,1,
    0.5f,0.5f,0.5f,0.5f,0.5f,0.5f,0.0f,0.5f,0.5f,
    0.5f,0.5f,0.5f,0.5f,
    0.5f,0.5f,0.5f,0.5f,0.5f,0.5f,0.5f,0.5f,0.0f,
    0.5f,0.5f,0.5f,0.5f,
    0.5f,0.5f,0.5f,0.5f,0.5f,0.0f,0.5f,0.5f,0.5f,
    0.5f,0.5f,0.5f,0.5f,
    0.5f,0.5f,0.5f,0.5f,0.5f,0.5f,0.5f,0.0f,0.5f,
    0.5f,0.5f,0.5f,0.5f,
    1,1,1,1,1,1,1
};

__constant__ float cC1[NSLOT] = {
    0,0,0,0,0,0,0,0,
    0.5f,0.5f,0.5f,0.5f,0.5f,0.5f,0.5f,0.5f,0.0f,0.0f,0.5f,
    0,0,0,0,0,0,0,
    0.0f,0.5f,0.5f,0.5f,0.5f,0.5f,0.5f,0.5f,0.0f,
    0.0f,0.5f,0.5f,0.5f,
    0.0f,0.5f,0.5f,0.5f,0.0f,0.5f,0.5f,0.5f,0.5f,
    0.0f,0.5f,0.5f,0.5f,
    0.5f,0.0f,0.5f,0.5f,0.5f,0.5f,0.5f,0.0f,0.5f,
    0.0f,0.5f,0.5f,0.5f,
    0.5f,0.0f,0.5f,0.0f,0.5f,0.5f,0.5f,0.5f,0.5f,
    0.0f,0.5f,0.5f,0.5f,
    0,0,0,0,0,0,0
};

// Folded weights, fp16, dense [s][k][oc=128][ci=64]
__device__ __align__(16) __half g_Wh[(size_t)NSLOT * 15 * 8192];

// ---------------------------------------------------------------------------
// smem (bytes):
//   [0,512)      pooled bias (128 f32)
//   [512,+38880) A: [parity(2)][q=135][72 halves], pitch 144B
//   [39392,+73728) B: 4 buffers x 18432B ([oc=128][72 halves])
// Epilogue reuses [512,...) as D staging [128][132 f32] (67584B).
// ---------------------------------------------------------------------------
#define AP    72
#define AROWS 135
#define ASZ   (AROWS * AP)             // 9720 halves per parity
#define A_OFF 512
#define B_OFF (A_OFF + 2 * ASZ * 2)    // 39392
#define BSZB  18432
#define NBUF  4
#define SMEM_BYTES (B_OFF + NBUF * BSZB)   // 113120

__device__ __forceinline__ uint32_t smem_u32(const void* p) {
    uint32_t a;
    asm("{ .reg .u64 t; cvta.to.shared.u64 t, %1; cvt.u32.u64 %0, t; }" : "=r"(a) : "l"(p));
    return a;
}

__device__ __forceinline__ void mma16816(float* d, const uint32_t* a,
                                         uint32_t b0, uint32_t b1) {
    asm volatile(
        "mma.sync.aligned.m16n8k16.row.col.f32.f16.f16.f32 "
        "{%0,%1,%2,%3}, {%4,%5,%6,%7}, {%8,%9}, {%0,%1,%2,%3};"
        : "+f"(d[0]), "+f"(d[1]), "+f"(d[2]), "+f"(d[3])
        : "r"(a[0]), "r"(a[1]), "r"(a[2]), "r"(a[3]), "r"(b0), "r"(b1));
}

__device__ __forceinline__ void ldmx4(uint32_t* r, uint32_t addr) {
    asm volatile("ldmatrix.sync.aligned.m8n8.x4.shared.b16 {%0,%1,%2,%3}, [%4];"
                 : "=r"(r[0]), "=r"(r[1]), "=r"(r[2]), "=r"(r[3]) : "r"(addr));
}

// ---------------------------------------------------------------------------
__global__ void prep_wc(const float* __restrict__ weight) {
    const int s  = blockIdx.x;
    const int oc = blockIdx.y;
    const int g  = cSlotG[s];
    const int j  = cJ[s];
    const float c0 = cC0[s], c1 = cC1[s];
    const int e0 = cE0[g], e1 = cE1[g];

    const float* __restrict__ w0 = weight + (size_t)(e0 * 128 + oc) * 20160 + (size_t)j * 960;
    const float* __restrict__ w1 = (e1 >= 0)
        ? weight + (size_t)(e1 * 128 + oc) * 20160 + (size_t)j * 960 : nullptr;

    for (int q = threadIdx.x; q < 960; q += blockDim.x) {
        float v = c0 * w0[q];
        if (w1) v += c1 * w1[q];
        const int ci = q / 15;
        const int k  = q - ci * 15;
        g_Wh[((size_t)(s * 15 + k) * 128 + oc) * 64 + ci] = __float2half_rn(v);
    }
}

// ---------------------------------------------------------------------------
// Main: 256 threads, 8 warps (4 t x 2 oc), tile 128t x 128oc.
// ---------------------------------------------------------------------------
__global__ __launch_bounds__(256, 2)
void motion_hmma(const float* __restrict__ x,
                 const float* __restrict__ bias,
                 float* __restrict__ out) {
    extern __shared__ __align__(16) char smem[];
    float* sbias = reinterpret_cast<float*>(smem);
    __half* Aarr = reinterpret_cast<__half*>(smem + A_OFF);
    char* Bbase  = smem + B_OFF;
    const uint32_t Asm = smem_u32(Aarr);
    const uint32_t Bsm = smem_u32(Bbase);

    const int tid  = threadIdx.x;
    const int w    = tid >> 5;
    const int lane = tid & 31;

    const int tile = blockIdx.x;   // 0..15
    const int b    = blockIdx.y;   // 0..7
    const int g    = blockIdx.z;   // 0..11
    const int t0   = tile << 7;
    const int base = 2 * t0 - 7;

    const int warp_tm = (w & 3) * 32;
    const int warp_on = (w >> 2) * 64;

    if (tid < 128) {
        const int e0 = cE0[g], e1 = cE1[g];
        float bv = bias[e0 * 128 + tid];
        if (e1 >= 0) bv = 0.5f * (bv + bias[e1 * 128 + tid]);
        sbias[tid] = bv;
    }

    float acc[2][8][4];
#pragma unroll
    for (int mi = 0; mi < 2; ++mi)
#pragma unroll
        for (int ni = 0; ni < 8; ++ni)
#pragma unroll
            for (int q = 0; q < 4; ++q) acc[mi][ni][q] = 0.f;

    const int off0 = cOff[g];
    const int nj   = cOff[g + 1] - off0;
    const int nt   = nj * 15;

    // cp.async of tap n's B tile (18KB) into buf n&3
    auto issue = [&](int n) {
        const int s = off0 + n / 15;
        const int k = n - (n / 15) * 15;
        const size_t tbase = (size_t)(s * 15 + k) * 8192;
        const uint32_t dbase = Bsm + (uint32_t)(n & 3) * BSZB;
#pragma unroll
        for (int i = 0; i < 4; ++i) {
            const int c   = tid + (i << 8);       // 0..1023
            const int row = c >> 3;               // oc
            const int col = c & 7;                // 16B chunk
            const __half* src = g_Wh + tbase + (size_t)row * 64 + col * 8;
            const uint32_t dst = dbase + row * 144 + col * 16;
            asm volatile("cp.async.cg.shared.global [%0], [%1], 16;"
                         :: "r"(dst), "l"(src) : "memory");
        }
        asm volatile("cp.async.commit_group;" ::: "memory");
    };

    issue(0);
    if (nt > 1) issue(1);

    // per-lane ldmatrix address components
    const uint32_t aoff = (uint32_t)(lane & 15) * 144 + ((lane >> 4) ? 16u : 0u);
    const uint32_t boff = (uint32_t)(warp_on + ((lane >> 4) & 1) * 8 + (lane & 7)) * 144
                        + (((lane >> 3) & 1) ? 16u : 0u);

    for (int jj = 0; jj < nj; ++jj) {
        const int j = cJ[off0 + jj];

        __syncthreads();   // all warps done reading previous joint's A window

        // ---- window load: x -> Ah per parity ----
        {
            const float* __restrict__ xj = x + ((size_t)b * 1344 + (size_t)j * 64) * 4096;
            for (int ci = w; ci < 64; ci += 8) {
                const float* __restrict__ src = xj + (size_t)ci * 4096;
                for (int r = lane; r < 269; r += 32) {
                    int pos = base + r;
                    pos = pos < 0 ? -pos : pos;
                    pos = pos > 4095 ? 8190 - pos : pos;
                    Aarr[(size_t)(r & 1) * ASZ + (r >> 1) * AP + ci] =
                        __float2half_rn(src[pos]);
                }
            }
        }

        for (int k = 0; k < 15; ++k) {
            const int n = jj * 15 + k;
            if (n + 2 < nt) {
                issue(n + 2);
                asm volatile("cp.async.wait_group 2;" ::: "memory");
            } else {
                asm volatile("cp.async.wait_group 0;" ::: "memory");
            }
            __syncthreads();   // B[n] visible; A window visible (k==0); gates buf reuse

            const uint32_t Ap = Asm + (uint32_t)(k & 1) * (ASZ * 2)
                              + (uint32_t)(warp_tm + (k >> 1)) * 144 + aoff;
            const uint32_t Bp = Bsm + (uint32_t)(n & 3) * BSZB + boff;

#pragma unroll
            for (int cc = 0; cc < 4; ++cc) {
                uint32_t a[2][4];
                ldmx4(a[0], Ap + cc * 32);
                ldmx4(a[1], Ap + cc * 32 + 16 * 144);
#pragma unroll
                for (int p = 0; p < 4; ++p) {
                    uint32_t bb[4];
                    ldmx4(bb, Bp + cc * 32 + p * (16 * 144));
                    mma16816(acc[0][2 * p],     a[0], bb[0], bb[1]);
                    mma16816(acc[1][2 * p],     a[1], bb[0], bb[1]);
                    mma16816(acc[0][2 * p + 1], a[0], bb[2], bb[3]);
                    mma16816(acc[1][2 * p + 1], a[1], bb[2], bb[3]);
                }
            }
            // no trailing sync: 4 buffers + issue-ahead 2 keeps reuse safe
        }
    }

    __syncthreads();   // all MMAs done before staging overwrites A/B regions

    // ---- epilogue: transpose D via smem, bias + leaky relu ----
    float* Ds = reinterpret_cast<float*>(smem + A_OFF);   // [128][132]
    {
        const int grow = lane >> 2;
        const int colb = (lane & 3) * 2;
#pragma unroll
        for (int mi = 0; mi < 2; ++mi) {
            const int row = warp_tm + mi * 16 + grow;
#pragma unroll
            for (int ni = 0; ni < 8; ++ni) {
                const int col = warp_on + ni * 8 + colb;
                Ds[(col    ) * 132 + row    ] = acc[mi][ni][0];
                Ds[(col + 1) * 132 + row    ] = acc[mi][ni][1];
                Ds[(col    ) * 132 + row + 8] = acc[mi][ni][2];
                Ds[(col + 1) * 132 + row + 8] = acc[mi][ni][3];
            }
        }
    }
    __syncthreads();

    {
        const int oc = tid >> 1, half = tid & 1;
        const float bv = sbias[oc];
        const float4* __restrict__ sp =
            reinterpret_cast<const float4*>(Ds + oc * 132 + half * 64);
        float4* __restrict__ op = reinterpret_cast<float4*>(
            out + ((size_t)b * 1536 + (size_t)g * 128 + oc) * 2048 + t0 + half * 64);
#pragma unroll
        for (int i = 0; i < 16; ++i) {
            float4 v = sp[i];
            v.x += bv; v.y += bv; v.z += bv; v.w += bv;
            v.x = v.x > 0.f ? v.x : 0.2f * v.x;
            v.y = v.y > 0.f ? v.y : 0.2f * v.y;
            v.z = v.z > 0.f ? v.z : 0.2f * v.z;
            v.w = v.w > 0.f ? v.w : 0.2f * v.w;
            op[i] = v;
        }
    }
}

// ---------------------------------------------------------------------------
extern "C" void kernel_launch(void* const* d_in, const int* in_sizes, int n_in,
                              void* d_out, int out_size) {
    (void)in_sizes; (void)n_in; (void)out_size;
    const float* x      = (const float*)d_in[0];   // [8][1344][4096]
    const float* weight = (const float*)d_in[1];   // [2688][1344][15]
    const float* bias   = (const float*)d_in[2];   // [2688]
    float* out          = (float*)d_out;           // [8][1536][2048]

    cudaFuncSetAttribute(motion_hmma, cudaFuncAttributeMaxDynamicSharedMemorySize,
                         SMEM_BYTES);

    dim3 gp(NSLOT, 128);
    prep_wc<<<gp, 256>>>(weight);

    dim3 gm(16, 8, NG);
    motion_hmma<<<gm, 256, SMEM_BYTES>>>(x, bias, out);
}